// round 11
// baseline (speedup 1.0000x reference)
#include <cuda_runtime.h>
#include <cuda_fp16.h>
#include <stdint.h>

#define NB 8
#define NS 2048
#define ND 1024
#define NROWS (NB * NS)          // 16384
#define WSZ ((size_t)ND * ND)

// ---------------- scratch (no cudaMalloc allowed) ----------------
__device__ __half g_xn  [(size_t)NROWS * ND];
__device__ __half g_q   [(size_t)NROWS * ND];
__device__ __half g_k   [(size_t)NROWS * ND];
__device__ __half g_kT  [(size_t)NROWS * ND];
__device__ __half g_w   [(size_t)NB * NS * NS];
__device__ __half g_at  [(size_t)NROWS * ND];
__device__ float  g_x2  [(size_t)NROWS * ND];
__device__ __half g_xn2 [(size_t)NROWS * ND];
__device__ __half g_h   [(size_t)NROWS * ND];
__device__ __half g_wt  [5 * WSZ];   // 5 transposed fp16 weights

// ---------------- helpers ----------------
__device__ __forceinline__ uint32_t smem_u32(const void* p) {
    uint32_t a;
    asm("{ .reg .u64 t; cvta.to.shared.u64 t, %1; cvt.u32.u64 %0, t; }" : "=r"(a) : "l"(p));
    return a;
}
__device__ __forceinline__ void cp16(uint32_t dst, const void* src) {
    asm volatile("cp.async.cg.shared.global [%0], [%1], 16;" :: "r"(dst), "l"(src));
}
__device__ __forceinline__ void ldmA(uint32_t* a, uint32_t addr) {
    asm volatile("ldmatrix.sync.aligned.m8n8.x4.shared.b16 {%0,%1,%2,%3}, [%4];"
                 : "=r"(a[0]), "=r"(a[1]), "=r"(a[2]), "=r"(a[3]) : "r"(addr));
}
__device__ __forceinline__ void ldmB(uint32_t* b, uint32_t addr) {
    asm volatile("ldmatrix.sync.aligned.m8n8.x2.shared.b16 {%0,%1}, [%2];"
                 : "=r"(b[0]), "=r"(b[1]) : "r"(addr));
}
__device__ __forceinline__ void mma16816(float* c, const uint32_t* a, const uint32_t* b) {
    asm volatile("mma.sync.aligned.m16n8k16.row.col.f32.f16.f16.f32 "
                 "{%0,%1,%2,%3}, {%4,%5,%6,%7}, {%8,%9}, {%0,%1,%2,%3};"
                 : "+f"(c[0]), "+f"(c[1]), "+f"(c[2]), "+f"(c[3])
                 : "r"(a[0]), "r"(a[1]), "r"(a[2]), "r"(a[3]), "r"(b[0]), "r"(b[1]));
}

#define NSTG 3
#define STAGE 24576u               // A 8K (64 rows x 64k) | B 16K (128 rows x 64k)
#define SMEMSZ (NSTG * STAGE)      // 72 KB -> 3 CTAs/SM (216 KB)
// A block: 8 row-tiles;  B block: 16 row-tiles (8x8 fp16 tiles, 128B each)
__device__ __forceinline__ uint32_t toffA(int rt8, int kt8) {
    return (uint32_t)((kt8 * 8 + rt8) * 128);
}
__device__ __forceinline__ uint32_t toffB(int rt8, int kt8) {
    return (uint32_t)((kt8 * 16 + rt8) * 128);
}

// ---------------- warp-MMA fp16 GEMM: 64x128 CTA tile, kchunk 64, 1 pass ----------------
// D = alpha * A[M,K](fp16) * B[N,K]^T  (+bias) (mask==0 -> -1e9) (+resid) (relu)
// 8 warps as 2(m) x 4(n), warp tile 32x32.  OUT: 0 = fp32, 1 = fp16
template <bool BIAS, bool RELU, bool MASK, bool RESID, int OUT>
__global__ void __launch_bounds__(256, 3) gemm_tc(
    const __half* __restrict__ A,
    const __half* __restrict__ B,
    int M, int N, int K,
    long long sA, long long sB, long long sC,
    float* __restrict__ Cf,
    __half* __restrict__ Ch,
    const float* __restrict__ bias,
    const float* __restrict__ resid,
    const int* __restrict__ mask,
    float alpha)
{
    extern __shared__ char smem[];
    const int tid  = threadIdx.x;
    const int lane = tid & 31, wid = tid >> 5;
    const int wm = wid & 1, wn = wid >> 1;          // 2 x 4 warp grid, warp tile 32x32
    const int bz = blockIdx.z;
    A += (size_t)bz * sA; B += (size_t)bz * sB;
    const size_t coff = (size_t)bz * sC;
    if (OUT == 0) Cf += coff; else Ch += coff;
    const int m0 = blockIdx.y * 64, n0 = blockIdx.x * 128;

    const uint32_t sb = smem_u32(smem);

    float acc[2][4][4];
#pragma unroll
    for (int i = 0; i < 2; i++)
#pragma unroll
        for (int j = 0; j < 4; j++)
#pragma unroll
            for (int q = 0; q < 4; q++) acc[i][j][q] = 0.f;

    const int nk = K >> 6;                           // 64-wide chunks

    // staging maps (row = idx>>3, kt8 = idx&7; 64 cols = 8 k-tiles)
    const int sa_row = tid >> 3, s_kt = tid & 7;     // A: 256 idx -> rows 0..31 x2
    uint32_t da[2]; int ra[2];
#pragma unroll
    for (int h = 0; h < 2; h++) {
        const int r = sa_row + h * 32;
        ra[h] = r;
        da[h] = (uint32_t)((s_kt * 8 + (r >> 3)) * 128 + (r & 7) * 16);
    }
    uint32_t db[4]; int rb[4];
#pragma unroll
    for (int h = 0; h < 4; h++) {
        const int r = sa_row + h * 32;               // B rows 0..127
        rb[h] = r;
        db[h] = (uint32_t)((s_kt * 16 + (r >> 3)) * 128 + (r & 7) * 16);
    }

    auto issue = [&](int i) {
        const uint32_t s = sb + (uint32_t)(i % NSTG) * STAGE;
        const int k0 = i << 6;
#pragma unroll
        for (int h = 0; h < 2; h++)
            cp16(s + da[h], A + (size_t)(m0 + ra[h]) * K + k0 + s_kt * 8);
#pragma unroll
        for (int h = 0; h < 4; h++)
            cp16(s + 8192 + db[h], B + (size_t)(n0 + rb[h]) * K + k0 + s_kt * 8);
        asm volatile("cp.async.commit_group;");
    };

    issue(0);
    issue(1);
    const int mrow16 = (lane & 7) * 16;
    const int bmi = (lane >> 3) & 1;                 // B x2 k-subtile select
    const int dm = (lane >> 3) & 1, dk = lane >> 4;  // A x4 decode

    for (int i = 0; i < nk; i++) {
        if (i == nk - 1) asm volatile("cp.async.wait_group 0;");
        else             asm volatile("cp.async.wait_group 1;");
        __syncthreads();
        if (i + 2 < nk) issue(i + 2);

        const uint32_t st  = sb + (uint32_t)(i % NSTG) * STAGE;
        const uint32_t sAa = st;
        const uint32_t sBb = st + 8192;

#pragma unroll
        for (int ks = 0; ks < 4; ks++) {             // 4 k16 subtiles per 64-chunk
            uint32_t a[2][4];
#pragma unroll
            for (int mt = 0; mt < 2; mt++) {
                const int mt8 = wm * 4 + mt * 2 + dm;
                ldmA(a[mt], sAa + toffA(mt8, ks * 2 + dk) + mrow16);
            }
            uint32_t bh[4][2];
#pragma unroll
            for (int nt = 0; nt < 4; nt++)
                ldmB(bh[nt], sBb + toffB(wn * 4 + nt, ks * 2 + bmi) + mrow16);
            // 8 independent accumulators back-to-back
#pragma unroll
            for (int mt = 0; mt < 2; mt++)
#pragma unroll
                for (int nt = 0; nt < 4; nt++)
                    mma16816(acc[mt][nt], a[mt], bh[nt]);
        }
    }

    // ---------------- epilogue ----------------
    const int cq = (lane & 3) * 2, rq = lane >> 2;
#pragma unroll
    for (int nt = 0; nt < 4; nt++) {
        const int c = n0 + wn * 32 + nt * 8 + cq;
        float bv0 = 0.f, bv1 = 0.f;
        if (BIAS) { bv0 = bias[c]; bv1 = bias[c + 1]; }
        int mk0 = 1, mk1 = 1;
        if (MASK) {
            const int* mp = mask + (size_t)bz * N;
            mk0 = mp[c]; mk1 = mp[c + 1];
        }
#pragma unroll
        for (int mt = 0; mt < 2; mt++) {
            const int r0 = m0 + wm * 32 + mt * 16 + rq;
#pragma unroll
            for (int h = 0; h < 2; h++) {
                const int row = r0 + h * 8;
                float v0 = acc[mt][nt][h * 2 + 0] * alpha + bv0;
                float v1 = acc[mt][nt][h * 2 + 1] * alpha + bv1;
                if (MASK) { if (mk0 == 0) v0 = -1e9f; if (mk1 == 0) v1 = -1e9f; }
                if (RESID) {
                    float2 rv = *(const float2*)(resid + (size_t)row * N + c);
                    v0 += rv.x; v1 += rv.y;
                }
                if (RELU) { v0 = fmaxf(v0, 0.f); v1 = fmaxf(v1, 0.f); }
                if (OUT == 0) {
                    *(float2*)(Cf + (size_t)row * N + c) = make_float2(v0, v1);
                } else {
                    *(__half2*)(Ch + (size_t)row * N + c) =
                        __halves2half2(__float2half(v0), __float2half(v1));
                }
            }
        }
    }
}

// ---------------- LayerNorm -> fp16 ----------------
__global__ void __launch_bounds__(256) ln_f16(const float* __restrict__ x,
                                              const float* __restrict__ g,
                                              const float* __restrict__ b,
                                              __half* __restrict__ o)
{
    size_t row = blockIdx.x;
    int t = threadIdx.x;
    float4 xv = ((const float4*)(x + row * ND))[t];
    float s  = xv.x + xv.y + xv.z + xv.w;
    float ss = xv.x*xv.x + xv.y*xv.y + xv.z*xv.z + xv.w*xv.w;
#pragma unroll
    for (int off = 16; off; off >>= 1) {
        s  += __shfl_xor_sync(0xffffffffu, s,  off);
        ss += __shfl_xor_sync(0xffffffffu, ss, off);
    }
    __shared__ float sh_s[8], sh_ss[8];
    if ((t & 31) == 0) { sh_s[t >> 5] = s; sh_ss[t >> 5] = ss; }
    __syncthreads();
    float ts = 0.f, tss = 0.f;
#pragma unroll
    for (int i = 0; i < 8; i++) { ts += sh_s[i]; tss += sh_ss[i]; }
    float mean = ts * (1.f / ND);
    float var  = tss * (1.f / ND) - mean * mean;
    float rstd = rsqrtf(var + 1e-5f);
    float4 gv = ((const float4*)g)[t];
    float4 bv = ((const float4*)b)[t];
    float o0 = (xv.x - mean) * rstd * gv.x + bv.x;
    float o1 = (xv.y - mean) * rstd * gv.y + bv.y;
    float o2 = (xv.z - mean) * rstd * gv.z + bv.z;
    float o3 = (xv.w - mean) * rstd * gv.w + bv.w;
    __half2* ph = (__half2*)(o + row * ND);
    ph[2*t]   = __halves2half2(__float2half(o0), __float2half(o1));
    ph[2*t+1] = __halves2half2(__float2half(o2), __float2half(o3));
}

// ---------------- softmax (fp32 in-place) + fp16 emission ----------------
__global__ void __launch_bounds__(256) softmax_f16(float* __restrict__ w,
                                                   __half* __restrict__ o)
{
    float* p = w + (size_t)blockIdx.x * NS;
    int t = threadIdx.x;
    float4 v0 = ((const float4*)p)[t];
    float4 v1 = ((const float4*)p)[t + 256];
    float mx = fmaxf(fmaxf(fmaxf(v0.x, v0.y), fmaxf(v0.z, v0.w)),
                     fmaxf(fmaxf(v1.x, v1.y), fmaxf(v1.z, v1.w)));
#pragma unroll
    for (int off = 16; off; off >>= 1) mx = fmaxf(mx, __shfl_xor_sync(0xffffffffu, mx, off));
    __shared__ float shm[8], shs[8];
    if ((t & 31) == 0) shm[t >> 5] = mx;
    __syncthreads();
    mx = shm[0];
#pragma unroll
    for (int i = 1; i < 8; i++) mx = fmaxf(mx, shm[i]);
    float e[8];
    e[0] = __expf(v0.x - mx); e[1] = __expf(v0.y - mx);
    e[2] = __expf(v0.z - mx); e[3] = __expf(v0.w - mx);
    e[4] = __expf(v1.x - mx); e[5] = __expf(v1.y - mx);
    e[6] = __expf(v1.z - mx); e[7] = __expf(v1.w - mx);
    float s = e[0]+e[1]+e[2]+e[3]+e[4]+e[5]+e[6]+e[7];
#pragma unroll
    for (int off = 16; off; off >>= 1) s += __shfl_xor_sync(0xffffffffu, s, off);
    if ((t & 31) == 0) shs[t >> 5] = s;
    __syncthreads();
    s = 0.f;
#pragma unroll
    for (int i = 0; i < 8; i++) s += shs[i];
    float inv = 1.f / s;
#pragma unroll
    for (int i = 0; i < 8; i++) e[i] *= inv;
    ((float4*)p)[t]       = make_float4(e[0], e[1], e[2], e[3]);
    ((float4*)p)[t + 256] = make_float4(e[4], e[5], e[6], e[7]);

    __half2* ph = (__half2*)(o + (size_t)blockIdx.x * NS);
    ph[2*t]         = __halves2half2(__float2half(e[0]), __float2half(e[1]));
    ph[2*t+1]       = __halves2half2(__float2half(e[2]), __float2half(e[3]));
    ph[512 + 2*t]   = __halves2half2(__float2half(e[4]), __float2half(e[5]));
    ph[512 + 2*t+1] = __halves2half2(__float2half(e[6]), __float2half(e[7]));
}

// ---------------- 5 weight transposes in ONE launch: W[K,N] fp32 -> WT[N,K] fp16 ----------------
__global__ void __launch_bounds__(256) wt_conv5(
    const float* __restrict__ W0, const float* __restrict__ W1,
    const float* __restrict__ W2, const float* __restrict__ W3,
    const float* __restrict__ W4, __half* __restrict__ T)
{
    const float* W;
    switch (blockIdx.z) {
        case 0: W = W0; break;
        case 1: W = W1; break;
        case 2: W = W2; break;
        case 3: W = W3; break;
        default: W = W4; break;
    }
    __half* Th = T + (size_t)blockIdx.z * WSZ;
    __shared__ float tile[64][65];
    int k0 = blockIdx.y * 64, n0 = blockIdx.x * 64;
#pragma unroll
    for (int u = threadIdx.x; u < 4096; u += 256) {
        int r = u >> 6, c = u & 63;
        tile[r][c] = W[(size_t)(k0 + r) * ND + n0 + c];
    }
    __syncthreads();
#pragma unroll
    for (int u = threadIdx.x; u < 4096; u += 256) {
        int r = u >> 6, c = u & 63;
        Th[(size_t)(n0 + r) * ND + k0 + c] = __float2half(tile[c][r]);
    }
}

// ---------------- fp16 transpose (k -> kT per batch) ----------------
__global__ void __launch_bounds__(256) kt_kernel(const __half* __restrict__ ih,
                                                 __half* __restrict__ oh)
{
    __shared__ __half th[64][65];
    int b = blockIdx.z;
    int d0 = blockIdx.x * 64, s0 = blockIdx.y * 64;
    const size_t ib = (size_t)b * NS * ND;
    const size_t ob = (size_t)b * ND * NS;
#pragma unroll
    for (int u = threadIdx.x; u < 4096; u += 256) {
        int r = u >> 6, c = u & 63;
        th[r][c] = ih[ib + (size_t)(s0 + r) * ND + d0 + c];
    }
    __syncthreads();
#pragma unroll
    for (int u = threadIdx.x; u < 4096; u += 256) {
        int r = u >> 6, c = u & 63;
        oh[ob + (size_t)(d0 + r) * NS + s0 + c] = th[c][r];
    }
}

// ---------------- driver ----------------
extern "C" void kernel_launch(void* const* d_in, const int* in_sizes, int n_in,
                              void* d_out, int out_size)
{
    const float* x    = (const float*)d_in[0];
    const int*   mask = (const int*)  d_in[1];
    const float* ln1g = (const float*)d_in[2];
    const float* ln1b = (const float*)d_in[3];
    const float* Wq   = (const float*)d_in[4];
    const float* bq   = (const float*)d_in[5];
    const float* Wk   = (const float*)d_in[6];
    const float* bk   = (const float*)d_in[7];
    const float* Wo   = (const float*)d_in[8];
    const float* bo   = (const float*)d_in[9];
    const float* ln2g = (const float*)d_in[10];
    const float* ln2b = (const float*)d_in[11];
    const float* W1   = (const float*)d_in[12];
    const float* b1   = (const float*)d_in[13];
    const float* W2   = (const float*)d_in[14];
    const float* b2   = (const float*)d_in[15];

    float* out  = (float*)d_out;
    float* wout = out + (size_t)NROWS * ND;

    __half *xn, *q, *k, *kT, *w, *at, *xn2, *h, *wt;
    float* x2;
    cudaGetSymbolAddress((void**)&xn,  g_xn);
    cudaGetSymbolAddress((void**)&q,   g_q);
    cudaGetSymbolAddress((void**)&k,   g_k);
    cudaGetSymbolAddress((void**)&kT,  g_kT);
    cudaGetSymbolAddress((void**)&w,   g_w);
    cudaGetSymbolAddress((void**)&at,  g_at);
    cudaGetSymbolAddress((void**)&xn2, g_xn2);
    cudaGetSymbolAddress((void**)&h,   g_h);
    cudaGetSymbolAddress((void**)&x2,  g_x2);
    cudaGetSymbolAddress((void**)&wt,  g_wt);

    __half *wq_t = wt + 0*WSZ;
    __half *wk_t = wt + 1*WSZ;
    __half *wo_t = wt + 2*WSZ;
    __half *w1_t = wt + 3*WSZ;
    __half *w2_t = wt + 4*WSZ;

    cudaFuncSetAttribute(gemm_tc<true,false,false,false,1>,
                         cudaFuncAttributeMaxDynamicSharedMemorySize, SMEMSZ);
    cudaFuncSetAttribute(gemm_tc<false,false,true,false,0>,
                         cudaFuncAttributeMaxDynamicSharedMemorySize, SMEMSZ);
    cudaFuncSetAttribute(gemm_tc<false,false,false,false,1>,
                         cudaFuncAttributeMaxDynamicSharedMemorySize, SMEMSZ);
    cudaFuncSetAttribute(gemm_tc<true,false,false,true,0>,
                         cudaFuncAttributeMaxDynamicSharedMemorySize, SMEMSZ);
    cudaFuncSetAttribute(gemm_tc<true,true,false,false,1>,
                         cudaFuncAttributeMaxDynamicSharedMemorySize, SMEMSZ);

    // all 5 weight transposes in one launch
    wt_conv5<<<dim3(16, 16, 5), 256>>>(Wq, Wk, Wo, W1, W2, wt);

    // 1) xn = LN1(x)
    ln_f16<<<NROWS, 256>>>(x, ln1g, ln1b, xn);

    dim3 gP(ND / 128, NROWS / 64, 1);
    // 2) q = xn@Wq+bq ; k = xn@Wk+bk  (v == k, faithful reference bug)
    gemm_tc<true,false,false,false,1><<<gP, 256, SMEMSZ>>>(
        xn, wq_t, NROWS, ND, ND, 0, 0, 0,
        nullptr, q, bq, nullptr, nullptr, 1.f);
    gemm_tc<true,false,false,false,1><<<gP, 256, SMEMSZ>>>(
        xn, wk_t, NROWS, ND, ND, 0, 0, 0,
        nullptr, k, bk, nullptr, nullptr, 1.f);

    // 3) kT for attn@v
    kt_kernel<<<dim3(ND / 64, NS / 64, NB), 256>>>(k, kT);

    // 4) scores = (q @ k^T)/32, masked -> wout (fp32)
    dim3 gS(NS / 128, NS / 64, NB);
    gemm_tc<false,false,true,false,0><<<gS, 256, SMEMSZ>>>(
        q, k, NS, NS, ND,
        (long long)NS * ND, (long long)NS * ND, (long long)NS * NS,
        wout, nullptr, nullptr, nullptr, mask, 0.03125f);

    // 5) softmax in place + fp16 w
    softmax_f16<<<NROWS, 256>>>(wout, w);

    // 6) attn = w @ v  (v == k)
    dim3 gA(ND / 128, NS / 64, NB);
    gemm_tc<false,false,false,false,1><<<gA, 256, SMEMSZ>>>(
        w, kT, NS, ND, NS,
        (long long)NS * NS, (long long)ND * NS, (long long)NS * ND,
        nullptr, at, nullptr, nullptr, nullptr, 1.f);

    // 7) x2 = x + attn @ Wo + bo
    gemm_tc<true,false,false,true,0><<<gP, 256, SMEMSZ>>>(
        at, wo_t, NROWS, ND, ND, 0, 0, 0,
        x2, nullptr, bo, x, nullptr, 1.f);

    // 8) xn2 = LN2(x2)
    ln_f16<<<NROWS, 256>>>(x2, ln2g, ln2b, xn2);

    // 9) h = relu(xn2 @ W1 + b1)
    gemm_tc<true,true,false,false,1><<<gP, 256, SMEMSZ>>>(
        xn2, w1_t, NROWS, ND, ND, 0, 0, 0,
        nullptr, h, b1, nullptr, nullptr, 1.f);

    // 10) out = x2 + h @ W2 + b2
    gemm_tc<true,false,false,true,0><<<gP, 256, SMEMSZ>>>(
        h, w2_t, NROWS, ND, ND, 0, 0, 0,
        out, nullptr, b2, x2, nullptr, 1.f);
}

// round 12
// speedup vs baseline: 1.2598x; 1.2598x over previous
#include <cuda_runtime.h>
#include <cuda_fp16.h>
#include <stdint.h>

#define NB 8
#define NS 2048
#define ND 1024
#define NROWS (NB * NS)          // 16384
#define WSZ ((size_t)ND * ND)

// ---------------- scratch (no cudaMalloc allowed) ----------------
__device__ __half g_xn  [(size_t)NROWS * ND];
__device__ __half g_q   [(size_t)NROWS * ND];
__device__ __half g_k   [(size_t)NROWS * ND];
__device__ __half g_kT  [(size_t)NROWS * ND];
__device__ __half g_w   [(size_t)NB * NS * NS];
__device__ __half g_at  [(size_t)NROWS * ND];
__device__ float  g_x2  [(size_t)NROWS * ND];
__device__ __half g_xn2 [(size_t)NROWS * ND];
__device__ __half g_h   [(size_t)NROWS * ND];
__device__ __half g_wt  [5 * WSZ];   // 5 transposed fp16 weights

// ---------------- helpers ----------------
__device__ __forceinline__ uint32_t smem_u32(const void* p) {
    uint32_t a;
    asm("{ .reg .u64 t; cvta.to.shared.u64 t, %1; cvt.u32.u64 %0, t; }" : "=r"(a) : "l"(p));
    return a;
}
__device__ __forceinline__ void cp16(uint32_t dst, const void* src) {
    asm volatile("cp.async.cg.shared.global [%0], [%1], 16;" :: "r"(dst), "l"(src));
}
__device__ __forceinline__ void ldmA(uint32_t* a, uint32_t addr) {
    asm volatile("ldmatrix.sync.aligned.m8n8.x4.shared.b16 {%0,%1,%2,%3}, [%4];"
                 : "=r"(a[0]), "=r"(a[1]), "=r"(a[2]), "=r"(a[3]) : "r"(addr));
}
__device__ __forceinline__ void ldmB(uint32_t* b, uint32_t addr) {
    asm volatile("ldmatrix.sync.aligned.m8n8.x2.shared.b16 {%0,%1}, [%2];"
                 : "=r"(b[0]), "=r"(b[1]) : "r"(addr));
}
__device__ __forceinline__ void mma16816(float* c, const uint32_t* a, const uint32_t* b) {
    asm volatile("mma.sync.aligned.m16n8k16.row.col.f32.f16.f16.f32 "
                 "{%0,%1,%2,%3}, {%4,%5,%6,%7}, {%8,%9}, {%0,%1,%2,%3};"
                 : "+f"(c[0]), "+f"(c[1]), "+f"(c[2]), "+f"(c[3])
                 : "r"(a[0]), "r"(a[1]), "r"(a[2]), "r"(a[3]), "r"(b[0]), "r"(b[1]));
}

#define NSTG 3
#define STAGE 32768u               // A 16K | B 16K  (kchunk = 64)
#define SMEMSZ (NSTG * STAGE)      // 96 KB -> 2 CTAs/SM
// tile offset inside a 16K operand block: 8x8 fp16 tiles, id = kt8*16 + rt8
__device__ __forceinline__ uint32_t toff(int rt8, int kt8) {
    return (uint32_t)((kt8 * 16 + rt8) * 128);
}

// ---------------- warp-MMA fp16 GEMM: 128x128 CTA tile, kchunk 64, 1 pass ----------------
// Software-pipelined fragments: B double-buffered across ks, A across mt.
// D = alpha * A[M,K](fp16) * B[N,K]^T  (+bias) (mask==0 -> -1e9) (+resid) (relu)
// OUT: 0 = fp32, 1 = fp16
template <bool BIAS, bool RELU, bool MASK, bool RESID, int OUT>
__global__ void __launch_bounds__(256, 2) gemm_tc(
    const __half* __restrict__ A,
    const __half* __restrict__ B,
    int M, int N, int K,
    long long sA, long long sB, long long sC,
    float* __restrict__ Cf,
    __half* __restrict__ Ch,
    const float* __restrict__ bias,
    const float* __restrict__ resid,
    const int* __restrict__ mask,
    float alpha)
{
    extern __shared__ char smem[];
    const int tid  = threadIdx.x;
    const int lane = tid & 31, wid = tid >> 5;
    const int wm = wid & 1, wn = wid >> 1;          // 2 x 4 warp grid, warp tile 64x32
    const int bz = blockIdx.z;
    A += (size_t)bz * sA; B += (size_t)bz * sB;
    const size_t coff = (size_t)bz * sC;
    if (OUT == 0) Cf += coff; else Ch += coff;
    const int m0 = blockIdx.y * 128, n0 = blockIdx.x * 128;

    const uint32_t sb = smem_u32(smem);

    float acc[4][4][4];
#pragma unroll
    for (int i = 0; i < 4; i++)
#pragma unroll
        for (int j = 0; j < 4; j++)
#pragma unroll
            for (int q = 0; q < 4; q++) acc[i][j][q] = 0.f;

    const int nk = K >> 6;                           // 64-wide chunks

    // staging map: idx = tid + h*256 -> row = idx>>3, kt8 = idx&7 (64 cols = 8 k-tiles)
    const int s_row = tid >> 3, s_kt = tid & 7;
    uint32_t doff[4];
    int      srow[4];
#pragma unroll
    for (int h = 0; h < 4; h++) {
        const int r = s_row + h * 32;                // 4 x 32 rows = 128
        srow[h] = r;
        doff[h] = (uint32_t)((s_kt * 16 + (r >> 3)) * 128 + (r & 7) * 16);
    }

    auto issue = [&](int i) {
        const uint32_t s = sb + (uint32_t)(i % NSTG) * STAGE;
        const int k0 = i << 6;
#pragma unroll
        for (int h = 0; h < 4; h++) {
            const size_t ga = (size_t)(m0 + srow[h]) * K + k0 + s_kt * 8;
            const size_t gb = (size_t)(n0 + srow[h]) * K + k0 + s_kt * 8;
            cp16(s + doff[h],         A + ga);
            cp16(s + 16384 + doff[h], B + gb);
        }
        asm volatile("cp.async.commit_group;");
    };

    issue(0);
    issue(1);
    const int mrow16 = (lane & 7) * 16;
    const int bmi = (lane >> 3) & 1;                 // B x2 k-subtile select
    const int dm = (lane >> 3) & 1, dk = lane >> 4;  // A x4 decode

    for (int i = 0; i < nk; i++) {
        if (i == nk - 1) asm volatile("cp.async.wait_group 0;");
        else             asm volatile("cp.async.wait_group 1;");
        __syncthreads();
        if (i + 2 < nk) issue(i + 2);

        const uint32_t st  = sb + (uint32_t)(i % NSTG) * STAGE;
        const uint32_t sAa = st;
        const uint32_t sBb = st + 16384;

        // --- software-pipelined fragment consumption ---
        uint32_t bf[2][4][2];   // B frags: [ks parity][nt][2]
        uint32_t af[2][4];      // A frags: [mt parity][4]

        // prime B for ks = 0
#pragma unroll
        for (int nt = 0; nt < 4; nt++)
            ldmB(bf[0][nt], sBb + toff(wn * 4 + nt, 0 * 2 + bmi) + mrow16);

#pragma unroll
        for (int ks = 0; ks < 4; ks++) {
            const int kc = ks & 1;
            // prime A for mt = 0 of this ks
            ldmA(af[0], sAa + toff(wm * 8 + 0 * 2 + dm, ks * 2 + dk) + mrow16);
            // prefetch B for ks+1 (covered by this ks's 16 MMAs)
            if (ks < 3) {
#pragma unroll
                for (int nt = 0; nt < 4; nt++)
                    ldmB(bf[kc ^ 1][nt],
                         sBb + toff(wn * 4 + nt, (ks + 1) * 2 + bmi) + mrow16);
            }
#pragma unroll
            for (int mt = 0; mt < 4; mt++) {
                const int mc = mt & 1;
                // prefetch A for mt+1 (covered by 4 MMAs below)
                if (mt < 3) {
                    const int mt8 = wm * 8 + (mt + 1) * 2 + dm;
                    ldmA(af[mc ^ 1], sAa + toff(mt8, ks * 2 + dk) + mrow16);
                }
#pragma unroll
                for (int nt = 0; nt < 4; nt++)
                    mma16816(acc[mt][nt], af[mc], bf[kc][nt]);
            }
        }
    }

    // ---------------- epilogue ----------------
    const int cq = (lane & 3) * 2, rq = lane >> 2;
#pragma unroll
    for (int nt = 0; nt < 4; nt++) {
        const int c = n0 + wn * 32 + nt * 8 + cq;
        float bv0 = 0.f, bv1 = 0.f;
        if (BIAS) { bv0 = bias[c]; bv1 = bias[c + 1]; }
        int mk0 = 1, mk1 = 1;
        if (MASK) {
            const int* mp = mask + (size_t)bz * N;
            mk0 = mp[c]; mk1 = mp[c + 1];
        }
#pragma unroll
        for (int mt = 0; mt < 4; mt++) {
            const int r0 = m0 + wm * 64 + mt * 16 + rq;
#pragma unroll
            for (int h = 0; h < 2; h++) {
                const int row = r0 + h * 8;
                float v0 = acc[mt][nt][h * 2 + 0] * alpha + bv0;
                float v1 = acc[mt][nt][h * 2 + 1] * alpha + bv1;
                if (MASK) { if (mk0 == 0) v0 = -1e9f; if (mk1 == 0) v1 = -1e9f; }
                if (RESID) {
                    float2 rv = *(const float2*)(resid + (size_t)row * N + c);
                    v0 += rv.x; v1 += rv.y;
                }
                if (RELU) { v0 = fmaxf(v0, 0.f); v1 = fmaxf(v1, 0.f); }
                if (OUT == 0) {
                    *(float2*)(Cf + (size_t)row * N + c) = make_float2(v0, v1);
                } else {
                    *(__half2*)(Ch + (size_t)row * N + c) =
                        __halves2half2(__float2half(v0), __float2half(v1));
                }
            }
        }
    }
}

// ---------------- LayerNorm -> fp16 ----------------
__global__ void __launch_bounds__(256) ln_f16(const float* __restrict__ x,
                                              const float* __restrict__ g,
                                              const float* __restrict__ b,
                                              __half* __restrict__ o)
{
    size_t row = blockIdx.x;
    int t = threadIdx.x;
    float4 xv = ((const float4*)(x + row * ND))[t];
    float s  = xv.x + xv.y + xv.z + xv.w;
    float ss = xv.x*xv.x + xv.y*xv.y + xv.z*xv.z + xv.w*xv.w;
#pragma unroll
    for (int off = 16; off; off >>= 1) {
        s  += __shfl_xor_sync(0xffffffffu, s,  off);
        ss += __shfl_xor_sync(0xffffffffu, ss, off);
    }
    __shared__ float sh_s[8], sh_ss[8];
    if ((t & 31) == 0) { sh_s[t >> 5] = s; sh_ss[t >> 5] = ss; }
    __syncthreads();
    float ts = 0.f, tss = 0.f;
#pragma unroll
    for (int i = 0; i < 8; i++) { ts += sh_s[i]; tss += sh_ss[i]; }
    float mean = ts * (1.f / ND);
    float var  = tss * (1.f / ND) - mean * mean;
    float rstd = rsqrtf(var + 1e-5f);
    float4 gv = ((const float4*)g)[t];
    float4 bv = ((const float4*)b)[t];
    float o0 = (xv.x - mean) * rstd * gv.x + bv.x;
    float o1 = (xv.y - mean) * rstd * gv.y + bv.y;
    float o2 = (xv.z - mean) * rstd * gv.z + bv.z;
    float o3 = (xv.w - mean) * rstd * gv.w + bv.w;
    __half2* ph = (__half2*)(o + row * ND);
    ph[2*t]   = __halves2half2(__float2half(o0), __float2half(o1));
    ph[2*t+1] = __halves2half2(__float2half(o2), __float2half(o3));
}

// ---------------- softmax (fp32 in-place) + fp16 emission ----------------
__global__ void __launch_bounds__(256) softmax_f16(float* __restrict__ w,
                                                   __half* __restrict__ o)
{
    float* p = w + (size_t)blockIdx.x * NS;
    int t = threadIdx.x;
    float4 v0 = ((const float4*)p)[t];
    float4 v1 = ((const float4*)p)[t + 256];
    float mx = fmaxf(fmaxf(fmaxf(v0.x, v0.y), fmaxf(v0.z, v0.w)),
                     fmaxf(fmaxf(v1.x, v1.y), fmaxf(v1.z, v1.w)));
#pragma unroll
    for (int off = 16; off; off >>= 1) mx = fmaxf(mx, __shfl_xor_sync(0xffffffffu, mx, off));
    __shared__ float shm[8], shs[8];
    if ((t & 31) == 0) shm[t >> 5] = mx;
    __syncthreads();
    mx = shm[0];
#pragma unroll
    for (int i = 1; i < 8; i++) mx = fmaxf(mx, shm[i]);
    float e[8];
    e[0] = __expf(v0.x - mx); e[1] = __expf(v0.y - mx);
    e[2] = __expf(v0.z - mx); e[3] = __expf(v0.w - mx);
    e[4] = __expf(v1.x - mx); e[5] = __expf(v1.y - mx);
    e[6] = __expf(v1.z - mx); e[7] = __expf(v1.w - mx);
    float s = e[0]+e[1]+e[2]+e[3]+e[4]+e[5]+e[6]+e[7];
#pragma unroll
    for (int off = 16; off; off >>= 1) s += __shfl_xor_sync(0xffffffffu, s, off);
    if ((t & 31) == 0) shs[t >> 5] = s;
    __syncthreads();
    s = 0.f;
#pragma unroll
    for (int i = 0; i < 8; i++) s += shs[i];
    float inv = 1.f / s;
#pragma unroll
    for (int i = 0; i < 8; i++) e[i] *= inv;
    ((float4*)p)[t]       = make_float4(e[0], e[1], e[2], e[3]);
    ((float4*)p)[t + 256] = make_float4(e[4], e[5], e[6], e[7]);

    __half2* ph = (__half2*)(o + (size_t)blockIdx.x * NS);
    ph[2*t]         = __halves2half2(__float2half(e[0]), __float2half(e[1]));
    ph[2*t+1]       = __halves2half2(__float2half(e[2]), __float2half(e[3]));
    ph[512 + 2*t]   = __halves2half2(__float2half(e[4]), __float2half(e[5]));
    ph[512 + 2*t+1] = __halves2half2(__float2half(e[6]), __float2half(e[7]));
}

// ---------------- 5 weight transposes in ONE launch: W[K,N] fp32 -> WT[N,K] fp16 ----------------
__global__ void __launch_bounds__(256) wt_conv5(
    const float* __restrict__ W0, const float* __restrict__ W1,
    const float* __restrict__ W2, const float* __restrict__ W3,
    const float* __restrict__ W4, __half* __restrict__ T)
{
    const float* W;
    switch (blockIdx.z) {
        case 0: W = W0; break;
        case 1: W = W1; break;
        case 2: W = W2; break;
        case 3: W = W3; break;
        default: W = W4; break;
    }
    __half* Th = T + (size_t)blockIdx.z * WSZ;
    __shared__ float tile[64][65];
    int k0 = blockIdx.y * 64, n0 = blockIdx.x * 64;
#pragma unroll
    for (int u = threadIdx.x; u < 4096; u += 256) {
        int r = u >> 6, c = u & 63;
        tile[r][c] = W[(size_t)(k0 + r) * ND + n0 + c];
    }
    __syncthreads();
#pragma unroll
    for (int u = threadIdx.x; u < 4096; u += 256) {
        int r = u >> 6, c = u & 63;
        Th[(size_t)(n0 + r) * ND + k0 + c] = __float2half(tile[c][r]);
    }
}

// ---------------- fp16 transpose (k -> kT per batch) ----------------
__global__ void __launch_bounds__(256) kt_kernel(const __half* __restrict__ ih,
                                                 __half* __restrict__ oh)
{
    __shared__ __half th[64][65];
    int b = blockIdx.z;
    int d0 = blockIdx.x * 64, s0 = blockIdx.y * 64;
    const size_t ib = (size_t)b * NS * ND;
    const size_t ob = (size_t)b * ND * NS;
#pragma unroll
    for (int u = threadIdx.x; u < 4096; u += 256) {
        int r = u >> 6, c = u & 63;
        th[r][c] = ih[ib + (size_t)(s0 + r) * ND + d0 + c];
    }
    __syncthreads();
#pragma unroll
    for (int u = threadIdx.x; u < 4096; u += 256) {
        int r = u >> 6, c = u & 63;
        oh[ob + (size_t)(d0 + r) * NS + s0 + c] = th[c][r];
    }
}

// ---------------- driver ----------------
extern "C" void kernel_launch(void* const* d_in, const int* in_sizes, int n_in,
                              void* d_out, int out_size)
{
    const float* x    = (const float*)d_in[0];
    const int*   mask = (const int*)  d_in[1];
    const float* ln1g = (const float*)d_in[2];
    const float* ln1b = (const float*)d_in[3];
    const float* Wq   = (const float*)d_in[4];
    const float* bq   = (const float*)d_in[5];
    const float* Wk   = (const float*)d_in[6];
    const float* bk   = (const float*)d_in[7];
    const float* Wo   = (const float*)d_in[8];
    const float* bo   = (const float*)d_in[9];
    const float* ln2g = (const float*)d_in[10];
    const float* ln2b = (const float*)d_in[11];
    const float* W1   = (const float*)d_in[12];
    const float* b1   = (const float*)d_in[13];
    const float* W2   = (const float*)d_in[14];
    const float* b2   = (const float*)d_in[15];

    float* out  = (float*)d_out;
    float* wout = out + (size_t)NROWS * ND;

    __half *xn, *q, *k, *kT, *w, *at, *xn2, *h, *wt;
    float* x2;
    cudaGetSymbolAddress((void**)&xn,  g_xn);
    cudaGetSymbolAddress((void**)&q,   g_q);
    cudaGetSymbolAddress((void**)&k,   g_k);
    cudaGetSymbolAddress((void**)&kT,  g_kT);
    cudaGetSymbolAddress((void**)&w,   g_w);
    cudaGetSymbolAddress((void**)&at,  g_at);
    cudaGetSymbolAddress((void**)&xn2, g_xn2);
    cudaGetSymbolAddress((void**)&h,   g_h);
    cudaGetSymbolAddress((void**)&x2,  g_x2);
    cudaGetSymbolAddress((void**)&wt,  g_wt);

    __half *wq_t = wt + 0*WSZ;
    __half *wk_t = wt + 1*WSZ;
    __half *wo_t = wt + 2*WSZ;
    __half *w1_t = wt + 3*WSZ;
    __half *w2_t = wt + 4*WSZ;

    cudaFuncSetAttribute(gemm_tc<true,false,false,false,1>,
                         cudaFuncAttributeMaxDynamicSharedMemorySize, SMEMSZ);
    cudaFuncSetAttribute(gemm_tc<false,false,true,false,0>,
                         cudaFuncAttributeMaxDynamicSharedMemorySize, SMEMSZ);
    cudaFuncSetAttribute(gemm_tc<false,false,false,false,1>,
                         cudaFuncAttributeMaxDynamicSharedMemorySize, SMEMSZ);
    cudaFuncSetAttribute(gemm_tc<true,false,false,true,0>,
                         cudaFuncAttributeMaxDynamicSharedMemorySize, SMEMSZ);
    cudaFuncSetAttribute(gemm_tc<true,true,false,false,1>,
                         cudaFuncAttributeMaxDynamicSharedMemorySize, SMEMSZ);

    // all 5 weight transposes in one launch
    wt_conv5<<<dim3(16, 16, 5), 256>>>(Wq, Wk, Wo, W1, W2, wt);

    // 1) xn = LN1(x)
    ln_f16<<<NROWS, 256>>>(x, ln1g, ln1b, xn);

    dim3 gP(ND / 128, NROWS / 128, 1);
    // 2) q = xn@Wq+bq ; k = xn@Wk+bk  (v == k, faithful reference bug)
    gemm_tc<true,false,false,false,1><<<gP, 256, SMEMSZ>>>(
        xn, wq_t, NROWS, ND, ND, 0, 0, 0,
        nullptr, q, bq, nullptr, nullptr, 1.f);
    gemm_tc<true,false,false,false,1><<<gP, 256, SMEMSZ>>>(
        xn, wk_t, NROWS, ND, ND, 0, 0, 0,
        nullptr, k, bk, nullptr, nullptr, 1.f);

    // 3) kT for attn@v
    kt_kernel<<<dim3(ND / 64, NS / 64, NB), 256>>>(k, kT);

    // 4) scores = (q @ k^T)/32, masked -> wout (fp32)
    dim3 gS(NS / 128, NS / 128, NB);
    gemm_tc<false,false,true,false,0><<<gS, 256, SMEMSZ>>>(
        q, k, NS, NS, ND,
        (long long)NS * ND, (long long)NS * ND, (long long)NS * NS,
        wout, nullptr, nullptr, nullptr, mask, 0.03125f);

    // 5) softmax in place + fp16 w
    softmax_f16<<<NROWS, 256>>>(wout, w);

    // 6) attn = w @ v  (v == k)
    dim3 gA(ND / 128, NS / 128, NB);
    gemm_tc<false,false,false,false,1><<<gA, 256, SMEMSZ>>>(
        w, kT, NS, ND, NS,
        (long long)NS * NS, (long long)ND * NS, (long long)NS * ND,
        nullptr, at, nullptr, nullptr, nullptr, 1.f);

    // 7) x2 = x + attn @ Wo + bo
    gemm_tc<true,false,false,true,0><<<gP, 256, SMEMSZ>>>(
        at, wo_t, NROWS, ND, ND, 0, 0, 0,
        x2, nullptr, bo, x, nullptr, 1.f);

    // 8) xn2 = LN2(x2)
    ln_f16<<<NROWS, 256>>>(x2, ln2g, ln2b, xn2);

    // 9) h = relu(xn2 @ W1 + b1)
    gemm_tc<true,true,false,false,1><<<gP, 256, SMEMSZ>>>(
        xn2, w1_t, NROWS, ND, ND, 0, 0, 0,
        nullptr, h, b1, nullptr, nullptr, 1.f);

    // 10) out = x2 + h @ W2 + b2
    gemm_tc<true,false,false,true,0><<<gP, 256, SMEMSZ>>>(
        h, w2_t, NROWS, ND, ND, 0, 0, 0,
        out, nullptr, b2, x2, nullptr, 1.f);
}